// round 9
// baseline (speedup 1.0000x reference)
#include <cuda_runtime.h>
#include <math.h>

#define BATCH 128
#define N 256
#define NT 128
#define NP1 (N + 1)
#define NUM_CLASSES 8
#define CE_COEFF 10.0f
#define UNCLAIMED 0x7FFFFFFF
#define BIGF 1e30f
#define VMASK 0xFFFFFF00u

__device__ float g_batch_loss[BATCH];

__device__ __forceinline__ float fsqrt_approx(float x) {
    float r;
    asm("sqrt.approx.f32 %0, %1;" : "=f"(r) : "f"(x));
    return r;
}
__device__ __forceinline__ unsigned umin2(unsigned a, unsigned b) { return a < b ? a : b; }
__device__ __forceinline__ unsigned umax2(unsigned a, unsigned b) { return a > b ? a : b; }

// One CTA per batch, 128 threads.
// Phase 1  : column reduction (128 thr, 2 cols/thread).
// Phase 1.5: JV augmenting row reduction, 2 passes (128 thr).
// Phase 2  : exact shortest-augmenting-path on WARP 0 ONLY, 8 cols/lane,
//            all Dijkstra state in registers, REDUX argmin, NO barriers.
// Phase 3  : fused loss epilogue (128 thr).
__global__ __launch_bounds__(NT, 1) void hungarian_loss_kernel(
    const float* __restrict__ set1,   // [B, N, 3]
    const float* __restrict__ set2)   // [B, N, 10]
{
    const int b    = blockIdx.x;
    const int tid  = threadIdx.x;
    const int lane = tid & 31;
    const int wid  = tid >> 5;
    const int j0c  = tid + 1;          // 1-based column ids (phases 1/1.5)
    const int j1c  = tid + 129;

    __shared__ float s1x[N], s1y[N], s1l[N];
    __shared__ float s2x[N], s2y[N];
    __shared__ float u[NP1];
    __shared__ __align__(16) float4 rowdat[NP1]; // per column j: {x,y,u,row} of p[j]
    __shared__ int   way[NP1];
    __shared__ float vcol[N];                    // column duals (phase boundary spill)
    __shared__ int   rowclaim[N];
    __shared__ int   listA[N], listB[N];
    __shared__ unsigned warpmask[8];
    __shared__ int   snfree, snext;
    __shared__ __align__(16) unsigned red1[2][4];
    __shared__ __align__(16) unsigned red2s[2][4];
    __shared__ float swsum[4];

    const float* s1p = set1 + (size_t)b * N * 3;
    const float* s2p = set2 + (size_t)b * N * 10;

    #pragma unroll
    for (int q = 0; q < 2; ++q) {
        const int e = tid + q * NT;
        s1x[e] = s1p[e * 3 + 0];
        s1y[e] = s1p[e * 3 + 1];
        s1l[e] = s1p[e * 3 + 2];
        s2x[e] = s2p[e * 10 + 0];
        s2y[e] = s2p[e * 10 + 1];
        u[e]   = 0.0f;
        rowdat[e + 1] = make_float4(0.f, 0.f, 0.f, __int_as_float(0));
        rowclaim[e]   = UNCLAIMED;
    }
    if (tid == 0) { u[N] = 0.0f; rowdat[0] = make_float4(0.f, 0.f, 0.f, __int_as_float(0)); }
    __syncthreads();

    const float cx0 = s2x[tid],       cy0 = s2y[tid];
    const float cx1 = s2x[tid + NT],  cy1 = s2y[tid + NT];
    float v0, v1;                     // column duals (phases 1/1.5)

    // ---- Phase 1: column reduction ----
    {
        float bd0 = BIGF, bd1 = BIGF;
        int   bi0 = 0,    bi1 = 0;
        #pragma unroll 4
        for (int i = 0; i < N; ++i) {
            const float sx = s1x[i], sy = s1y[i];
            const float dx0 = sx - cx0, dy0 = sy - cy0;
            const float d20 = fmaf(dx0, dx0, dy0 * dy0);
            if (d20 < bd0) { bd0 = d20; bi0 = i; }
            const float dx1 = sx - cx1, dy1 = sy - cy1;
            const float d21 = fmaf(dx1, dx1, dy1 * dy1);
            if (d21 < bd1) { bd1 = d21; bi1 = i; }
        }
        v0 = fsqrt_approx(fmaxf(bd0, 0.0f));
        v1 = fsqrt_approx(fmaxf(bd1, 0.0f));
        atomicMin(&rowclaim[bi0], tid);
        atomicMin(&rowclaim[bi1], tid + NT);
        __syncthreads();
        if (rowclaim[bi0] == tid)
            rowdat[j0c] = make_float4(s1x[bi0], s1y[bi0], 0.0f, __int_as_float(bi0 + 1));
        if (rowclaim[bi1] == tid + NT)
            rowdat[j1c] = make_float4(s1x[bi1], s1y[bi1], 0.0f, __int_as_float(bi1 + 1));
        const bool f0 = (rowclaim[tid] == UNCLAIMED);
        const bool f1 = (rowclaim[tid + NT] == UNCLAIMED);
        const unsigned wm0 = __ballot_sync(0xffffffffu, f0);
        const unsigned wm1 = __ballot_sync(0xffffffffu, f1);
        if (lane == 0) { warpmask[wid] = wm0; warpmask[wid + 4] = wm1; }
        __syncthreads();
        int base0 = 0, base1 = 0, tot = 0;
        #pragma unroll
        for (int w = 0; w < 8; ++w) {
            const int c = __popc(warpmask[w]);
            if (w < wid)     base0 += c;
            if (w < wid + 4) base1 += c;
            tot += c;
        }
        const unsigned lm = (1u << lane) - 1u;
        if (f0) listA[base0 + __popc(wm0 & lm)] = tid + 1;
        if (f1) listA[base1 + __popc(wm1 & lm)] = tid + NT + 1;
        if (tid == 0) snfree = tot;
        __syncthreads();
    }

    // ---- Phase 1.5: augmenting row reduction (2 passes) ----
    int ncur = snfree;
    {
        int par = 0;
        for (int run = 0; run < 2; ++run) {
            int* cur = (run == 0) ? listA : listB;
            int* nxt = (run == 0) ? listB : listA;
            if (tid == 0) snext = 0;
            __syncthreads();
            for (int t = 0; t < ncur; ++t) {
                const int i = cur[t];
                const float sx = s1x[i - 1], sy = s1y[i - 1];
                const float dx0 = sx - cx0, dy0 = sy - cy0;
                const float rc0 = fmaxf(fsqrt_approx(fmaf(dx0, dx0, dy0 * dy0)) - v0, 0.0f);
                const float dx1 = sx - cx1, dy1 = sy - cy1;
                const float rc1 = fmaxf(fsqrt_approx(fmaf(dx1, dx1, dy1 * dy1)) - v1, 0.0f);
                const unsigned b0 = (__float_as_uint(rc0) & VMASK) | (unsigned)tid;
                const unsigned b1 = (__float_as_uint(rc1) & VMASK) | (unsigned)(tid + NT);
                const unsigned bmin = umin2(b0, b1);
                const unsigned bmax = umax2(b0, b1);
                const unsigned m1w  = __reduce_min_sync(0xffffffffu, bmin);
                const unsigned b2   = (bmin == m1w) ? bmax : bmin;
                const unsigned m2w  = __reduce_min_sync(0xffffffffu, b2);
                if (lane == 0) { red1[par][wid] = m1w; red2s[par][wid] = m2w; }
                __syncthreads();
                const uint4 r1 = *(const uint4*)&red1[par][0];
                const unsigned bp = umin2(umin2(r1.x, r1.y), umin2(r1.z, r1.w));
                const uint4 r2 = *(const uint4*)&red2s[par][0];
                unsigned sec = 0xFFFFFFFFu;
                sec = umin2(sec, (r1.x == bp) ? r2.x : r1.x);
                sec = umin2(sec, (r1.y == bp) ? r2.y : r1.y);
                sec = umin2(sec, (r1.z == bp) ? r2.z : r1.z);
                sec = umin2(sec, (r1.w == bp) ? r2.w : r1.w);
                const int   jone = (int)(bp & 0xFFu) + 1;
                const float m1   = __uint_as_float(bp & VMASK);
                const float m2   = __uint_as_float(sec & VMASK);
                if (tid == ((jone - 1) & (NT - 1))) {   // owner thread
                    const int k = __float_as_int(rowdat[jone].w);
                    if (m1 < m2) {
                        if (jone - 1 < NT) v0 -= (m2 - m1); else v1 -= (m2 - m1);
                        rowdat[jone] = make_float4(sx, sy, m2, __int_as_float(i));
                        u[i] = m2;
                        if (k != 0) { nxt[snext] = k; snext = snext + 1; }
                    } else {
                        if (k == 0) {
                            rowdat[jone] = make_float4(sx, sy, m2, __int_as_float(i));
                            u[i] = m2;
                        } else { nxt[snext] = i; snext = snext + 1; }
                    }
                }
                par ^= 1;
            }
            __syncthreads();
            ncur = snext;
            __syncthreads();
        }
    }
    // spill column duals for warp 0
    vcol[tid]      = v0;
    vcol[tid + NT] = v1;
    __syncthreads();

    // ---- Phase 2: augmenting paths, WARP 0 ONLY, 8 cols/lane, no barriers ----
    if (wid == 0) {
        float vx[8], cxr[8], cyr[8];
        #pragma unroll
        for (int c = 0; c < 8; ++c) {
            const int col = lane + 32 * c;
            vx[c]  = vcol[col];
            cxr[c] = s2x[col];
            cyr[c] = s2y[col];
        }

        for (int idx = 0; idx < ncur; ++idx) {
            const int ifree = listA[idx];

            unsigned db[8];
            int      wy[8];
            float    dmv[8];
            int      prv[8];
            #pragma unroll
            for (int c = 0; c < 8; ++c) { db[c] = 0xFFFFFFFFu; wy[c] = 0; dmv[c] = 0.f; prv[c] = 0; }
            unsigned usedmask = 0;

            int   jprev = 0;
            int   jfin;
            float rx = s1x[ifree - 1];
            float ry = s1y[ifree - 1];
            float u0 = u[ifree];
            float D  = 0.0f;

            while (true) {
                const float base = D - u0;
                unsigned rmin = 0xFFFFFFFFu;
                #pragma unroll
                for (int c = 0; c < 8; ++c) {
                    const float dx = rx - cxr[c];
                    const float dy = ry - cyr[c];
                    const float cost = fsqrt_approx(fmaf(dx, dx, dy * dy));
                    const float cand = fmaxf(base + (cost - vx[c]), D);
                    const unsigned cb = (__float_as_uint(cand) & VMASK) |
                                        (unsigned)(lane + 32 * c);
                    const bool un = !((usedmask >> c) & 1u);
                    const bool bt = (cb < db[c]) & un;
                    db[c] = bt ? cb : db[c];
                    wy[c] = bt ? jprev : wy[c];
                    rmin  = umin2(rmin, un ? db[c] : 0xFFFFFFFFu);
                }

                const unsigned best = __reduce_min_sync(0xffffffffu, rmin);
                D = __uint_as_float(best & VMASK);
                const int jz = (int)(best & 0xFFu);   // 0-based selected column
                const int jn = jz + 1;

                const float4 rd = rowdat[jn];
                const int pj = __float_as_int(rd.w);

                // publish way for the selected column (owner lane)
                int wsel = wy[0];
                #pragma unroll
                for (int c = 1; c < 8; ++c)
                    wsel = (jz == lane + 32 * c) ? wy[c] : wsel;
                if ((jz & 31) == lane) way[jn] = wsel;

                if (pj == 0) { jfin = jn; break; }   // uniform branch

                // mark jn used (owner lane, branchless per-col selects)
                const bool owner = ((jz & 31) == lane);
                usedmask |= owner ? (1u << (jz >> 5)) : 0u;
                #pragma unroll
                for (int c = 0; c < 8; ++c) {
                    const bool mk = (jz == lane + 32 * c);
                    dmv[c] = mk ? D  : dmv[c];
                    prv[c] = mk ? pj : prv[c];
                }

                jprev = jn;
                rx = rd.x;
                ry = rd.y;
                u0 = rd.z;
            }

            // deferred dual updates (distinct rows/cols across lanes -> race-free)
            #pragma unroll
            for (int c = 0; c < 8; ++c) {
                if ((usedmask >> c) & 1u) {
                    const float diff = D - dmv[c];
                    vx[c] -= diff;
                    const float un = u[prv[c]] + diff;
                    u[prv[c]] = un;
                    rowdat[lane + 32 * c + 1].z = un;
                }
            }
            if (lane == 0) u[ifree] += D;
            __syncwarp();

            if (lane == 0) {
                int jj = jfin;
                while (jj != 0) {
                    const int jp = way[jj];
                    if (jp == 0) {
                        rowdat[jj] = make_float4(s1x[ifree - 1], s1y[ifree - 1],
                                                 u[ifree], __int_as_float(ifree));
                    } else {
                        rowdat[jj] = rowdat[jp];
                    }
                    jj = jp;
                }
            }
            __syncwarp();
        }
    }
    __syncthreads();

    // ---- Phase 3: loss epilogue, 2 columns per thread ----
    float mds = 0.0f, nlls = 0.0f, cnts = 0.0f;
    #pragma unroll
    for (int q = 0; q < 2; ++q) {
        const int col = tid + q * NT;
        const float4 rdf = rowdat[col + 1];
        const int r = __float_as_int(rdf.w) - 1;

        const float dxm = rdf.x - s2x[col];
        const float dym = rdf.y - s2y[col];
        mds += fsqrt_approx(fmaxf(fmaf(dxm, dxm, dym * dym), 0.0f));

        float lg[NUM_CLASSES];
        float mx = -1e30f;
        #pragma unroll
        for (int k = 0; k < NUM_CLASSES; ++k) {
            lg[k] = s2p[col * 10 + 2 + k];
            mx = fmaxf(mx, lg[k]);
        }
        float se = 0.0f;
        #pragma unroll
        for (int k = 0; k < NUM_CLASSES; ++k) se += expf(lg[k] - mx);
        const float lse = mx + logf(se);

        const int  t    = (int)s1l[r];
        const bool mask = (t != -1);
        const int  st   = mask ? ((t < 0) ? 0 : (t >= NUM_CLASSES ? NUM_CLASSES - 1 : t)) : 0;
        nlls += mask ? (lse - lg[st]) : 0.0f;
        cnts += mask ? 1.0f : 0.0f;
    }

    float sv[3] = { mds, nlls, cnts };
    #pragma unroll
    for (int q = 0; q < 3; ++q) {
        float vv = sv[q];
        #pragma unroll
        for (int off = 16; off > 0; off >>= 1)
            vv += __shfl_down_sync(0xffffffffu, vv, off);
        if (lane == 0) swsum[wid] = vv;
        __syncthreads();
        if (tid == 0) sv[q] = swsum[0] + swsum[1] + swsum[2] + swsum[3];
        __syncthreads();
    }

    if (tid == 0) {
        const float loss1 = sv[0] / (float)N;
        const float denom = fmaxf(sv[2], 1.0f);
        const float loss2 = CE_COEFF * (sv[1] / denom);
        g_batch_loss[b] = loss1 + loss2;
    }
}

__global__ void finalize_kernel(float* __restrict__ out) {
    __shared__ float s[BATCH];
    const int t = threadIdx.x;
    s[t] = g_batch_loss[t];
    __syncthreads();
    #pragma unroll
    for (int off = BATCH / 2; off > 0; off >>= 1) {
        if (t < off) s[t] += s[t + off];
        __syncthreads();
    }
    if (t == 0) out[0] = s[0];
}

extern "C" void kernel_launch(void* const* d_in, const int* in_sizes, int n_in,
                              void* d_out, int out_size) {
    (void)in_sizes; (void)n_in; (void)out_size;
    const float* set1 = (const float*)d_in[0];
    const float* set2 = (const float*)d_in[1];
    float* out = (float*)d_out;

    hungarian_loss_kernel<<<BATCH, NT>>>(set1, set2);
    finalize_kernel<<<1, BATCH>>>(out);
}